// round 7
// baseline (speedup 1.0000x reference)
#include <cuda_runtime.h>
#include <math.h>

// AMPS fast log-prob, v5: bidirectional vector chains (no 4x4 chunk products).
//   logit[n+1][bs][p] = e0^T * (Prod_{m=0..n} A(n,m,bs)) * diag[n+1][:,p]
//   Split at h=(n+1)/2:  vL = e0^T A_0..A_{h-1}  (forward row-vector chain)
//                        uR_p = A_h..A_n diag_p  (backward column-vector chain)
//   logit = vL . uR_p.   A distributed via warp-private plane-split smem tiles.
// Left warp: 4 chains x 8 samples. Right warp: 2 chains x 8 samples x 2 cols.
// 96 CTAs = one wave. Then combine (dot+lse) and finalize (reduce).

#define NN    1024
#define NCH   1023
#define FULLM 0xffffffffu
#define TT    8
#define LBLK  32     // 32*8 warps * 4 chains = 1024
#define RBLK  64     // 64*8 warps * 2 chains = 1024
#define GSTR  260    // floats between left staging groups (1040B % 128 = 16: conflict-free)

__device__ float g_vL[NCH * 8 * 4];        // [n][bs][j]
__device__ float g_uR[NCH * 16 * 4];       // [n][bs*2+p][j]
__device__ float g_contrib[8 * 1024];      // [bs][pos]

__global__ __launch_bounds__(256) void amps_main(const float* __restrict__ data,
                                                 const float* __restrict__ tri,
                                                 const float* __restrict__ diag) {
    __shared__ unsigned ssel[NN];
    __shared__ float sbuf[8][4 * GSTR + 16];

    const int tid = threadIdx.x, warp = tid >> 5, lane = tid & 31;

    for (int m = tid; m < NN; m += 256) {
        unsigned s = 0;
#pragma unroll
        for (int b = 0; b < 8; b++) s |= ((data[b * NN + m] != 0.0f) ? 0u : 1u) << b;
        ssel[m] = s;
    }
    __syncthreads();

    const float4* tri4 = (const float4*)tri;
    float* wb = sbuf[warp];

    if (blockIdx.x < LBLK) {
        // ================= LEFT: v = e0^T A_0 .. A_{h-1} =================
        const int g = lane >> 3, bs = lane & 7;
        const int n = (blockIdx.x * 8 + warp) * 4 + g;
        const bool valid = (n < NCH);
        const int nc = valid ? n : (NCH - 1);
        const int h = valid ? ((nc + 1) >> 1) : 0;          // steps
        const int ws = __reduce_max_sync(FULLM, h);
        const size_t t0 = (size_t)nc * (nc + 1) / 2;
        const float4* base = tri4 + t0 * 8;
        const int sc = (h > 0) ? (h - 1) : 0;
        float* smg = wb + g * GSTR;

        float v0 = 1.0f, v1 = 0.0f, v2 = 0.0f, v3 = 0.0f;

        float4 r[TT];
#pragma unroll
        for (int t = 0; t < TT; t++) r[t] = __ldg(base + (size_t)min(t, sc) * 8 + bs);

        for (int mt = 0; mt < ws; mt += TT) {
            __syncwarp();
#pragma unroll
            for (int t = 0; t < TT; t++) {
                float4 w = r[t];
                *(float2*)(smg + t * 32 + bs * 2)      = make_float2(w.x, w.z);  // plane0
                *(float2*)(smg + t * 32 + 16 + bs * 2) = make_float2(w.y, w.w);  // plane1
            }
            __syncwarp();
            if (mt + TT < ws) {
#pragma unroll
                for (int t = 0; t < TT; t++)
                    r[t] = __ldg(base + (size_t)min(mt + TT + t, sc) * 8 + bs);
            }
#pragma unroll
            for (int t = 0; t < TT; t++) {
                const int m = mt + t;
                const int p = (ssel[m] >> bs) & 1;
                const float4* ap = (const float4*)(smg + t * 32 + p * 16);
                float4 a0 = ap[0], a1 = ap[1], a2 = ap[2], a3 = ap[3];
                if (m < h) {
                    float n0 = v0 * a0.x + v1 * a1.x + v2 * a2.x + v3 * a3.x;
                    float n1 = v0 * a0.y + v1 * a1.y + v2 * a2.y + v3 * a3.y;
                    float n2 = v0 * a0.z + v1 * a1.z + v2 * a2.z + v3 * a3.z;
                    float n3 = v0 * a0.w + v1 * a1.w + v2 * a2.w + v3 * a3.w;
                    v0 = n0; v1 = n1; v2 = n2; v3 = n3;
                }
            }
        }
        if (valid)
            *(float4*)&g_vL[(n * 8 + bs) * 4] = make_float4(v0, v1, v2, v3);
    } else {
        // ================= RIGHT: u = A_h .. A_n d_p (backward) =================
        const int gg = lane >> 4, sub = lane & 15, bs = sub & 7, pp = sub >> 3;
        const int n = ((blockIdx.x - LBLK) * 8 + warp) * 2 + gg;
        const bool valid = (n < NCH);
        const int nc = valid ? n : (NCH - 1);
        const int h = (nc + 1) >> 1;
        const int steps = valid ? (nc + 1 - h) : 0;          // m = n down to h
        const int ws = __reduce_max_sync(FULLM, steps);
        const size_t t0 = (size_t)nc * (nc + 1) / 2;
        const float4* base = tri4 + t0 * 8;
        float* smg = wb + gg * (2 * GSTR);

        // staging role: this lane loads line-slot lt, quarters q = hf*4+k
        const int lt = sub >> 1, hf = sub & 1;

        float u0, u1, u2, u3;
        {
            const float* dgp = diag + (size_t)(nc + 1) * 8 + pp;
            u0 = dgp[0]; u1 = dgp[2]; u2 = dgp[4]; u3 = dgp[6];
        }

        float4 r[4];
#pragma unroll
        for (int k = 0; k < 4; k++)
            r[k] = __ldg(base + (size_t)max(nc - lt, 0) * 8 + hf * 4 + k);

        for (int st = 0; st < ws; st += TT) {
            __syncwarp();
#pragma unroll
            for (int k = 0; k < 4; k++) {
                float4 w = r[k];
                const int q = hf * 4 + k;
                *(float2*)(smg + lt * 32 + q * 2)      = make_float2(w.x, w.z);
                *(float2*)(smg + lt * 32 + 16 + q * 2) = make_float2(w.y, w.w);
            }
            __syncwarp();
            if (st + TT < ws) {
#pragma unroll
                for (int k = 0; k < 4; k++)
                    r[k] = __ldg(base + (size_t)max(nc - (st + TT + lt), 0) * 8 + hf * 4 + k);
            }
#pragma unroll
            for (int t = 0; t < TT; t++) {
                const int s = st + t;
                const int m = nc - s;
                const int p = (ssel[m >= 0 ? m : 0] >> bs) & 1;
                const float4* ap = (const float4*)(smg + t * 32 + p * 16);
                float4 a0 = ap[0], a1 = ap[1], a2 = ap[2], a3 = ap[3];
                if (s < steps) {
                    float n0 = a0.x * u0 + a0.y * u1 + a0.z * u2 + a0.w * u3;
                    float n1 = a1.x * u0 + a1.y * u1 + a1.z * u2 + a1.w * u3;
                    float n2 = a2.x * u0 + a2.y * u1 + a2.z * u2 + a2.w * u3;
                    float n3 = a3.x * u0 + a3.y * u1 + a3.z * u2 + a3.w * u3;
                    u0 = n0; u1 = n1; u2 = n2; u3 = n3;
                }
            }
        }
        if (valid)
            *(float4*)&g_uR[(n * 16 + bs * 2 + pp) * 4] = make_float4(u0, u1, u2, u3);
    }
}

// ---------------- combine: logit = vL . uR_p ; fused log-softmax ----------------
__global__ __launch_bounds__(256) void amps_combine(const float* __restrict__ data) {
    const int tid = blockIdx.x * 256 + threadIdx.x;
    const int n = tid >> 3, bs = tid & 7;
    if (n >= NCH) return;

    float4 v = *(const float4*)&g_vL[(n * 8 + bs) * 4];
    float4 a = *(const float4*)&g_uR[(n * 16 + bs * 2 + 0) * 4];
    float4 b = *(const float4*)&g_uR[(n * 16 + bs * 2 + 1) * 4];
    float x0 = v.x * a.x + v.y * a.y + v.z * a.z + v.w * a.w;
    float x1 = v.x * b.x + v.y * b.y + v.z * b.z + v.w * b.w;
    float mx = fmaxf(x0, x1);
    float lse = mx + log1pf(expf(-fabsf(x0 - x1)));
    bool p1 = (data[bs * NN + (n + 1)] == 0.0f);
    g_contrib[bs * 1024 + n + 1] = (p1 ? x1 : x0) - lse;
}

// ---------------- finalize: parallel reduction per sample ----------------
__global__ void amps_finalize(const float* __restrict__ data, const float* __restrict__ diag,
                              float* __restrict__ out) {
    const int bs = blockIdx.x;
    const int tid = threadIdx.x, warp = tid >> 5, lane = tid & 31;
    float4 v = ((const float4*)(g_contrib + bs * 1024))[tid];
    if (tid == 0) {
        float x0 = diag[0], x1 = diag[1];
        float mx = fmaxf(x0, x1);
        float lse = mx + log1pf(expf(-fabsf(x0 - x1)));
        v.x = ((data[bs * NN] == 0.0f) ? x1 : x0) - lse;
    }
    float s = v.x + v.y + v.z + v.w;
#pragma unroll
    for (int o = 16; o; o >>= 1) s += __shfl_xor_sync(FULLM, s, o);
    __shared__ float ws8[8];
    if (lane == 0) ws8[warp] = s;
    __syncthreads();
    if (warp == 0) {
        float t = (lane < 8) ? ws8[lane] : 0.0f;
#pragma unroll
        for (int o = 4; o; o >>= 1) t += __shfl_xor_sync(FULLM, t, o);
        if (lane == 0) out[bs] = t;
    }
}

extern "C" void kernel_launch(void* const* d_in, const int* in_sizes, int n_in,
                              void* d_out, int out_size) {
    const float* data = (const float*)d_in[0];
    const float* tri  = (const float*)d_in[1];
    const float* diag = (const float*)d_in[2];
    float* out = (float*)d_out;

    amps_main<<<LBLK + RBLK, 256>>>(data, tri, diag);
    amps_combine<<<32, 256>>>(data);
    amps_finalize<<<8, 256>>>(data, diag, out);
}

// round 10
// speedup vs baseline: 1.9582x; 1.9582x over previous
#include <cuda_runtime.h>
#include <math.h>

// AMPS fast log-prob, v6: uniform 64-step chunks, 128-thr blocks (5 CTA/SM), f32x2 packed FMA.
//   chain(n, bs): v = e0^T * Prod_{m=0..n} A(n,m,bs);  A = plane-selected 4x4 of tri_up[n(n+1)/2+m]
//   logits[n+1][bs][p] = v . diag[n+1][:,p];  out[bs] = sum_n logsoftmax(logits[n])[sel]
// Main: work unit = 64-step 4x4 chunk product, lane = (chunk g, sample bs), P held as
//   4 row-pairs packed in f32x2 regs; A staged in smem pre-DUPLICATED per plane so each
//   step is 8 LDS.128 + 32 fma.f32x2 (no FSEL, no shfl).
// Combine: v = row0(P_0) @ P_1 @ ...; fused log-softmax.  Finalize: per-sample reduce.

#define NN    1024
#define NCH   1023
#define FULLM 0xffffffffu
#define TT    8
#define NCID  8688
#define NBLK  543      // ceil(8688 / 16)
#define CELL  72       // floats per (t, g) staging cell (64 + 8 skew)

typedef unsigned long long ull;

__device__ __forceinline__ ull fma2(ull a, ull b, ull c) {
    ull d; asm("fma.rn.f32x2 %0, %1, %2, %3;" : "=l"(d) : "l"(a), "l"(b), "l"(c)); return d;
}
__device__ __forceinline__ ull mul2(ull a, ull b) {
    ull d; asm("mul.rn.f32x2 %0, %1, %2;" : "=l"(d) : "l"(a), "l"(b)); return d;
}

__device__ float g_M[NCID * 128];        // [cid][bs*16 + i*4 + j]
__device__ float g_contrib[8 * 1024];    // [bs][pos]
__device__ unsigned g_sel[NN];           // bit bs = plane (0 if data!=0 else 1)

__constant__ int c_off[17] = {0,1023,1982,2877,3708,4475,5178,5817,6392,6903,
                              7350,7733,8052,8307,8498,8625,8688};

// ---------------- prep: selector bits ----------------
__global__ void amps_prep(const float* __restrict__ data) {
    int m = blockIdx.x * 128 + threadIdx.x;
    if (m < NN) {
        unsigned s = 0;
#pragma unroll
        for (int b = 0; b < 8; b++) s |= ((data[b * NN + m] != 0.0f) ? 0u : 1u) << b;
        g_sel[m] = s;
    }
}

// ---------------- main: 64-step chunk products ----------------
__global__ __launch_bounds__(128, 5) void amps_main(const float* __restrict__ tri) {
    __shared__ unsigned ssel[NN];
    __shared__ float sbuf[4][TT * 4 * CELL];   // [warp][(t*4+g)*CELL]

    const int tid = threadIdx.x, warp = tid >> 5, lane = tid & 31;
    const int g = lane >> 3, bs = lane & 7;

    for (int m = tid; m < NN; m += 128) ssel[m] = g_sel[m];
    __syncthreads();

    const float4* tri4 = (const float4*)tri;
    float* wb = sbuf[warp];

    const int cid = (blockIdx.x * 4 + warp) * 4 + g;
    const bool valid = (cid < NCID);
    const int cc = valid ? cid : 0;
    int c = 0;
#pragma unroll
    for (int j = 1; j < 16; j++) if (cc >= c_off[j]) c = j;
    const int n = 64 * c + (cc - c_off[c]);
    const int mS = 64 * c;
    const int steps = min(n, mS + 63) - mS + 1;
    const int ws = __reduce_max_sync(FULLM, steps);
    const size_t t0 = (size_t)n * (n + 1) / 2;
    const float4* base = tri4 + (t0 + mS) * 8;
    const int sc = steps - 1;

    // P rows packed in pairs: P2[ip*4+j] = (P[2ip][j], P[2ip+1][j]); init = identity
    ull P2[8];
    P2[0] = 0x000000003f800000ULL; P2[1] = 0x3f80000000000000ULL; P2[2] = 0; P2[3] = 0;
    P2[4] = 0; P2[5] = 0; P2[6] = 0x000000003f800000ULL; P2[7] = 0x3f80000000000000ULL;

    // loader role: this lane's float4 = quarters (row r, cols c0, c0+1), both planes
    const int lr = bs >> 1, lc = (bs & 1) * 2;

    float4 r[TT];
#pragma unroll
    for (int t = 0; t < TT; t++) r[t] = __ldg(base + (size_t)min(t, sc) * 8 + bs);

    for (int st = 0; st < ws; st += TT) {
        __syncwarp();
#pragma unroll
        for (int t = 0; t < TT; t++) {
            float* cell = wb + (t * 4 + g) * CELL;
            float4 w = r[t];
            // duplicated per-plane layout: cell[p*32 + j*8 + r*2] = (a[r][j][p], a[r][j][p])
            *(float2*)(cell + lc * 8 + lr * 2)            = make_float2(w.x, w.x);
            *(float2*)(cell + (lc + 1) * 8 + lr * 2)      = make_float2(w.z, w.z);
            *(float2*)(cell + 32 + lc * 8 + lr * 2)       = make_float2(w.y, w.y);
            *(float2*)(cell + 32 + (lc + 1) * 8 + lr * 2) = make_float2(w.w, w.w);
        }
        __syncwarp();
        if (st + TT < ws) {
#pragma unroll
            for (int t = 0; t < TT; t++)
                r[t] = __ldg(base + (size_t)min(st + TT + t, sc) * 8 + bs);
        }
#pragma unroll
        for (int t = 0; t < TT; t++) {
            const int s = st + t;
            const int p = (ssel[mS + s] >> bs) & 1;
            const float* ap = wb + (t * 4 + g) * CELL + p * 32;
            // A2[j*2+h]: h=0 -> (dup a0j, dup a1j), h=1 -> (dup a2j, dup a3j)
            ull A2[8];
#pragma unroll
            for (int j = 0; j < 4; j++) {
                float4 w0 = *(const float4*)(ap + j * 8);
                float4 w1 = *(const float4*)(ap + j * 8 + 4);
                A2[j * 2 + 0] = *(const ull*)&w0.x;  ull hi0 = *(const ull*)&w0.z;
                A2[j * 2 + 1] = *(const ull*)&w1.x;  ull hi1 = *(const ull*)&w1.z;
                // repack: A2[j*2] low pair = dup a0j, need dup a1j separately
                // w0 = (a0j,a0j,a1j,a1j): lo ull = dup a0j, hi ull = dup a1j
                // store as: A2[j*2] = dup a0j (k=0), hi0 = dup a1j (k=1),
                //           A2[j*2+1] = dup a2j (k=2), hi1 = dup a3j (k=3)
                if (s < steps) {
#pragma unroll
                    for (int ip = 0; ip < 2; ip++) {
                        // placeholder; real update below uses all k
                    }
                }
                // stash hi parts in registers via immediate use:
                // (computed in the update loop below)
                A2[j * 2 + 0] = A2[j * 2 + 0];  // dup a0j
                A2[j * 2 + 1] = hi0;            // dup a1j  (repurpose slot)
                // a2j/a3j handled via w1 regs: keep in two more regs
                ((ull*)&w0)[0] = *(const ull*)&w1.x;  // dup a2j
                ((ull*)&w0)[1] = hi1;                 // dup a3j
                if (s < steps) {
                    ull q0 = fma2(P2[0], A2[j*2+0], fma2(P2[1], A2[j*2+1],
                              fma2(P2[2], ((ull*)&w0)[0], mul2(P2[3], ((ull*)&w0)[1]))));
                    ull q1 = fma2(P2[4], A2[j*2+0], fma2(P2[5], A2[j*2+1],
                              fma2(P2[6], ((ull*)&w0)[0], mul2(P2[7], ((ull*)&w0)[1]))));
                    // defer write-back: accumulate into temporaries indexed by j
                    A2[j * 2 + 0] = q0;   // reuse A2 as Q storage
                    A2[j * 2 + 1] = q1;
                }
            }
            if (s < steps) {
                P2[0] = A2[0]; P2[1] = A2[2]; P2[2] = A2[4]; P2[3] = A2[6];
                P2[4] = A2[1]; P2[5] = A2[3]; P2[6] = A2[5]; P2[7] = A2[7];
            }
        }
    }
    if (valid) {
        // P2[ip*4+j] = (P[2ip][j], P[2ip+1][j])
        const float2* pf = (const float2*)P2;
        float4* dst = (float4*)&g_M[(size_t)cid * 128 + bs * 16];
        dst[0] = make_float4(pf[0].x, pf[1].x, pf[2].x, pf[3].x);
        dst[1] = make_float4(pf[0].y, pf[1].y, pf[2].y, pf[3].y);
        dst[2] = make_float4(pf[4].x, pf[5].x, pf[6].x, pf[7].x);
        dst[3] = make_float4(pf[4].y, pf[5].y, pf[6].y, pf[7].y);
    }
}

// ---------------- combine: v = row0(P_0) @ P_1 @ ... ; fused log-softmax ----------------
__global__ __launch_bounds__(256) void amps_combine(const float* __restrict__ data,
                                                    const float* __restrict__ diag) {
    const int warp = threadIdx.x >> 5, lane = threadIdx.x & 31;
    const int bs = lane >> 2, rr = lane & 3;
    const int n = blockIdx.x * 8 + warp;
    if (n >= NCH) return;

    float4 vv = *(const float4*)&g_M[(size_t)n * 128 + bs * 16];  // cid(n,0) = n, row 0
    float v0 = vv.x, v1 = vv.y, v2 = vv.z, v3 = vv.w;

    const int nch = (n >> 6) + 1;
    for (int c = 1; c < nch; c++) {
        const int cid = c_off[c] + n - 64 * c;
        const float* Mb = &g_M[(size_t)cid * 128 + bs * 16];
        float nv = v0 * Mb[rr] + v1 * Mb[4 + rr] + v2 * Mb[8 + rr] + v3 * Mb[12 + rr];
        int qb = lane & ~3;
        v0 = __shfl_sync(FULLM, nv, qb);
        v1 = __shfl_sync(FULLM, nv, qb + 1);
        v2 = __shfl_sync(FULLM, nv, qb + 2);
        v3 = __shfl_sync(FULLM, nv, qb + 3);
    }
    const float* dg = diag + (size_t)(n + 1) * 8;
    const int rp = rr & 1;
    float x = v0 * dg[rp] + v1 * dg[2 + rp] + v2 * dg[4 + rp] + v3 * dg[6 + rp];
    float x1 = __shfl_sync(FULLM, x, (lane & ~3) + 1);
    if (rr == 0) {
        float x0 = x;
        float mx = fmaxf(x0, x1);
        float lse = mx + log1pf(expf(-fabsf(x0 - x1)));
        bool p1 = (data[bs * NN + (n + 1)] == 0.0f);
        g_contrib[bs * 1024 + n + 1] = (p1 ? x1 : x0) - lse;
    }
}

// ---------------- finalize: parallel reduction per sample ----------------
__global__ void amps_finalize(const float* __restrict__ data, const float* __restrict__ diag,
                              float* __restrict__ out) {
    const int bs = blockIdx.x;
    const int tid = threadIdx.x, warp = tid >> 5, lane = tid & 31;
    float4 v = ((const float4*)(g_contrib + bs * 1024))[tid];
    if (tid == 0) {
        float x0 = diag[0], x1 = diag[1];
        float mx = fmaxf(x0, x1);
        float lse = mx + log1pf(expf(-fabsf(x0 - x1)));
        v.x = ((data[bs * NN] == 0.0f) ? x1 : x0) - lse;
    }
    float s = v.x + v.y + v.z + v.w;
#pragma unroll
    for (int o = 16; o; o >>= 1) s += __shfl_xor_sync(FULLM, s, o);
    __shared__ float ws8[8];
    if (lane == 0) ws8[warp] = s;
    __syncthreads();
    if (warp == 0) {
        float t = (lane < 8) ? ws8[lane] : 0.0f;
#pragma unroll
        for (int o = 4; o; o >>= 1) t += __shfl_xor_sync(FULLM, t, o);
        if (lane == 0) out[bs] = t;
    }
}

extern "C" void kernel_launch(void* const* d_in, const int* in_sizes, int n_in,
                              void* d_out, int out_size) {
    const float* data = (const float*)d_in[0];
    const float* tri  = (const float*)d_in[1];
    const float* diag = (const float*)d_in[2];
    float* out = (float*)d_out;

    amps_prep<<<8, 128>>>(data);
    amps_main<<<NBLK, 128>>>(tri);
    amps_combine<<<128, 256>>>(data, diag);
    amps_finalize<<<8, 256>>>(data, diag, out);
}

// round 11
// speedup vs baseline: 3.9043x; 1.9938x over previous
#include <cuda_runtime.h>
#include <math.h>

// AMPS fast log-prob, v8: uniform 64-step chunks, i-row-paired f32x2 state, 5 CTA/SM.
//   chain(n, bs): v = e0^T * Prod_{m=0..n} A(n,m,bs);  A = plane-selected 4x4 of tri_up[n(n+1)/2+m]
//   logits[n+1][bs][p] = v . diag[n+1][:,p];  out[bs] = sum_n logsoftmax(logits[n])[sel]
// Main: work unit = 64-step 4x4 chunk product; lane = (chunk g, sample bs).
//   State P2[ip][k] = (P[2ip][k], P[2ip+1][k]) packed f32x2 -> update = 8 LDS.128 + 32 fma.f32x2.
//   A staged per (t,g) cell: plane0 at +0, plane1 at +36, cell stride 88 floats (conflict-free).
// Combine: v = row0(P_0) @ P_1 @ ...; fused log-softmax; last block reduces (atomic counter).

#define NN    1024
#define NCH   1023
#define FULLM 0xffffffffu
#define TT    4
#define NCID  8688
#define NBLK  543      // ceil(8688 / 16)
#define CELL  88       // floats per (t,g) cell
#define POFF  36       // plane1 float offset within cell

typedef unsigned long long ull;

__device__ __forceinline__ ull fma2(ull a, ull b, ull c) {
    ull d; asm("fma.rn.f32x2 %0, %1, %2, %3;" : "=l"(d) : "l"(a), "l"(b), "l"(c)); return d;
}
__device__ __forceinline__ ull mul2(ull a, ull b) {
    ull d; asm("mul.rn.f32x2 %0, %1, %2;" : "=l"(d) : "l"(a), "l"(b)); return d;
}
__device__ __forceinline__ float lo2(ull a) { float2 f; asm("mov.b64 {%0,%1}, %2;" : "=f"(f.x), "=f"(f.y) : "l"(a)); return f.x; }
__device__ __forceinline__ float hi2(ull a) { float2 f; asm("mov.b64 {%0,%1}, %2;" : "=f"(f.x), "=f"(f.y) : "l"(a)); return f.y; }

__device__ float g_M[NCID * 128];        // [cid][bs*16 + i*4 + j]
__device__ float g_contrib[8 * 1024];    // [bs][pos]
__device__ unsigned g_sel[NN];           // bit bs = plane (0 if data!=0 else 1)
__device__ int g_count;

__constant__ int c_off[17] = {0,1023,1982,2877,3708,4475,5178,5817,6392,6903,
                              7350,7733,8052,8307,8498,8625,8688};

// ---------------- prep: selector bits + counter reset ----------------
__global__ void amps_prep(const float* __restrict__ data) {
    int m = blockIdx.x * 128 + threadIdx.x;
    if (m < NN) {
        unsigned s = 0;
#pragma unroll
        for (int b = 0; b < 8; b++) s |= ((data[b * NN + m] != 0.0f) ? 0u : 1u) << b;
        g_sel[m] = s;
    }
    if (m == 0) g_count = 0;
}

// ---------------- main: 64-step chunk products ----------------
__global__ __launch_bounds__(128, 5) void amps_main(const float* __restrict__ tri) {
    __shared__ unsigned ssel[NN];
    __shared__ float sbuf[4][TT * 4 * CELL];   // 4 warps x (t*4+g)*CELL

    const int tid = threadIdx.x, warp = tid >> 5, lane = tid & 31;
    const int g = lane >> 3, bs = lane & 7;

    for (int m = tid; m < NN; m += 128) ssel[m] = g_sel[m];
    __syncthreads();

    const float4* tri4 = (const float4*)tri;
    float* wb = sbuf[warp];

    const int cid = (blockIdx.x * 4 + warp) * 4 + g;
    const bool valid = (cid < NCID);
    const int cc = valid ? cid : 0;
    int c = 0;
#pragma unroll
    for (int j = 1; j < 16; j++) if (cc >= c_off[j]) c = j;
    const int n = 64 * c + (cc - c_off[c]);
    const int mS = 64 * c;
    const int steps = min(n, mS + 63) - mS + 1;
    const int ws = __reduce_max_sync(FULLM, steps);
    const size_t t0 = (size_t)n * (n + 1) / 2;
    const float4* base = tri4 + (t0 + mS) * 8;
    const int sc = steps - 1;

    // P2[ip*4+k] = (P[2ip][k], P[2ip+1][k]); init identity
    ull P2[8];
    P2[0] = 0x000000003f800000ULL; P2[1] = 0x3f80000000000000ULL; P2[2] = 0; P2[3] = 0;
    P2[4] = 0; P2[5] = 0; P2[6] = 0x000000003f800000ULL; P2[7] = 0x3f80000000000000ULL;

    // staging target offset for this lane: k = bs>>1 rows? no: lane's float4 = row l=bs>>1, cols r0,r0+1
    const int so = (bs >> 1) * 8 + (bs & 1) * 4;   // l*8 + r0*2

    float4 r[TT];
#pragma unroll
    for (int t = 0; t < TT; t++) r[t] = __ldg(base + (size_t)min(t, sc) * 8 + bs);

    for (int st = 0; st < ws; st += TT) {
        __syncwarp();
#pragma unroll
        for (int t = 0; t < TT; t++) {
            float* cell = wb + (t * 4 + g) * CELL;
            float4 w = r[t];
            *(float2*)(cell + so)            = make_float2(w.x, w.x);  // plane0 (k=l, j=r0)
            *(float2*)(cell + so + 2)        = make_float2(w.z, w.z);  // plane0 (j=r0+1)
            *(float2*)(cell + POFF + so)     = make_float2(w.y, w.y);  // plane1
            *(float2*)(cell + POFF + so + 2) = make_float2(w.w, w.w);
        }
        __syncwarp();
        if (st + TT < ws) {
#pragma unroll
            for (int t = 0; t < TT; t++)
                r[t] = __ldg(base + (size_t)min(st + TT + t, sc) * 8 + bs);
        }
#pragma unroll
        for (int t = 0; t < TT; t++) {
            const int s = st + t;
            const int p = (ssel[mS + s] >> bs) & 1;
            const float* ap = wb + (t * 4 + g) * CELL + p * POFF;
            float4 f[8];
#pragma unroll
            for (int q8 = 0; q8 < 8; q8++) f[q8] = ((const float4*)ap)[q8];
            // A(k,j): f[k*2 + (j>>1)], j even -> lo ull, odd -> hi ull
            if (s < steps) {
                ull q[8];
#pragma unroll
                for (int ip = 0; ip < 2; ip++) {
#pragma unroll
                    for (int j = 0; j < 4; j++) {
                        const int jh = j >> 1, jo = (j & 1) * 2;
                        ull a0 = *(const ull*)(((const float*)&f[0 * 2 + jh]) + jo);
                        ull a1 = *(const ull*)(((const float*)&f[1 * 2 + jh]) + jo);
                        ull a2 = *(const ull*)(((const float*)&f[2 * 2 + jh]) + jo);
                        ull a3 = *(const ull*)(((const float*)&f[3 * 2 + jh]) + jo);
                        q[ip * 4 + j] = fma2(P2[ip * 4 + 0], a0,
                                        fma2(P2[ip * 4 + 1], a1,
                                        fma2(P2[ip * 4 + 2], a2,
                                        mul2(P2[ip * 4 + 3], a3))));
                    }
                }
#pragma unroll
                for (int q8 = 0; q8 < 8; q8++) P2[q8] = q[q8];
            }
        }
    }
    if (valid) {
        // P2[ip*4+j] = (P[2ip][j], P[2ip+1][j])
        float4* dst = (float4*)&g_M[(size_t)cid * 128 + bs * 16];
        dst[0] = make_float4(lo2(P2[0]), lo2(P2[1]), lo2(P2[2]), lo2(P2[3]));
        dst[1] = make_float4(hi2(P2[0]), hi2(P2[1]), hi2(P2[2]), hi2(P2[3]));
        dst[2] = make_float4(lo2(P2[4]), lo2(P2[5]), lo2(P2[6]), lo2(P2[7]));
        dst[3] = make_float4(hi2(P2[4]), hi2(P2[5]), hi2(P2[6]), hi2(P2[7]));
    }
}

// ---------------- combine: v = row0(P_0) @ P_1 @ ...; lse; fused last-block reduce ----------------
__global__ __launch_bounds__(256) void amps_combine(const float* __restrict__ data,
                                                    const float* __restrict__ diag,
                                                    float* __restrict__ out) {
    const int warp = threadIdx.x >> 5, lane = threadIdx.x & 31;
    const int bs = lane >> 2, rr = lane & 3;
    const int n = blockIdx.x * 8 + warp;

    if (n < NCH) {
        float4 vv = *(const float4*)&g_M[(size_t)n * 128 + bs * 16];  // cid(n,0)=n, row 0
        float v0 = vv.x, v1 = vv.y, v2 = vv.z, v3 = vv.w;

        const int nch = (n >> 6) + 1;
        for (int c = 1; c < nch; c++) {
            const int cid = c_off[c] + n - 64 * c;
            const float* Mb = &g_M[(size_t)cid * 128 + bs * 16];
            float nv = v0 * Mb[rr] + v1 * Mb[4 + rr] + v2 * Mb[8 + rr] + v3 * Mb[12 + rr];
            int qb = lane & ~3;
            v0 = __shfl_sync(FULLM, nv, qb);
            v1 = __shfl_sync(FULLM, nv, qb + 1);
            v2 = __shfl_sync(FULLM, nv, qb + 2);
            v3 = __shfl_sync(FULLM, nv, qb + 3);
        }
        const float* dg = diag + (size_t)(n + 1) * 8;
        const int rp = rr & 1;
        float x = v0 * dg[rp] + v1 * dg[2 + rp] + v2 * dg[4 + rp] + v3 * dg[6 + rp];
        float x1 = __shfl_sync(FULLM, x, (lane & ~3) + 1);
        if (rr == 0) {
            float x0 = x;
            float mx = fmaxf(x0, x1);
            float lse = mx + log1pf(expf(-fabsf(x0 - x1)));
            bool p1 = (data[bs * NN + (n + 1)] == 0.0f);
            g_contrib[bs * 1024 + n + 1] = (p1 ? x1 : x0) - lse;
        }
    }

    // ---- last block reduces everything (deterministic order) ----
    __shared__ int sdone;
    __threadfence();
    __syncthreads();
    if (threadIdx.x == 0) sdone = (atomicAdd(&g_count, 1) == gridDim.x - 1) ? 1 : 0;
    __syncthreads();
    if (!sdone) return;
    __threadfence();

    const int rbs = threadIdx.x >> 5;   // warp = sample
    const int rl = threadIdx.x & 31;
    float acc = 0.0f;
    const float4* cb = (const float4*)(g_contrib + rbs * 1024);
#pragma unroll
    for (int it = 0; it < 8; it++) {
        float4 v = cb[it * 32 + rl];
        if (it == 0 && rl == 0) {
            float x0 = diag[0], x1 = diag[1];
            float mx = fmaxf(x0, x1);
            float lse = mx + log1pf(expf(-fabsf(x0 - x1)));
            v.x = ((data[rbs * NN] == 0.0f) ? x1 : x0) - lse;  // n=0 term
        }
        acc += v.x + v.y + v.z + v.w;
    }
#pragma unroll
    for (int o = 16; o; o >>= 1) acc += __shfl_xor_sync(FULLM, acc, o);
    if (rl == 0) out[rbs] = acc;
}

extern "C" void kernel_launch(void* const* d_in, const int* in_sizes, int n_in,
                              void* d_out, int out_size) {
    const float* data = (const float*)d_in[0];
    const float* tri  = (const float*)d_in[1];
    const float* diag = (const float*)d_in[2];
    float* out = (float*)d_out;

    amps_prep<<<8, 128>>>(data);
    amps_main<<<NBLK, 128>>>(tri);
    amps_combine<<<128, 256>>>(data, diag, out);
}